// round 1
// baseline (speedup 1.0000x reference)
#include <cuda_runtime.h>
#include <math.h>

// PureKernalMetricLogits: out[b,c] = 3*scale*exp(-(||x_b||^2+||w_c||^2-2 x_b.w_c)/1.2)
// scale = log(C-1)/max(mean_b exp(-metric[b,label_b]/1.2), 0.5)
//
// Key structure: metric >= (||x_b|| - ||w_c||)^2 (reverse triangle ineq).
// If that lower bound / 1.2 > 110, expf underflows to exactly 0.0f in BOTH
// the reference (jnp.exp on f32) and here, so we can write zeros without the
// dot product. A full fp32 fallback handles the general case.

#define BATCH 4096
#define DIM   512
#define CLS   10000
#define C4    (CLS / 4)   // 2500 float4 per row

__device__ float        g_x2[BATCH];
__device__ float        g_w2[CLS];
__device__ float        g_cor_sum;
__device__ unsigned int g_w2max_bits;   // max ||w_c||^2 as uint (nonneg float => monotone)
__device__ float        g_scale3;       // 3 * log(C-1) / max(mean cor, 0.5)

// ---------------------------------------------------------------- init
__global__ void k_init() {
    g_cor_sum    = 0.0f;
    g_w2max_bits = 0u;
}

// ---------------------------------------------------------------- norms
// One warp per row. Rows [0,BATCH) -> feat, [BATCH, BATCH+CLS) -> weights.
__global__ void k_norms(const float* __restrict__ feat,
                        const float* __restrict__ w) {
    int warp = (blockIdx.x * blockDim.x + threadIdx.x) >> 5;
    int lane = threadIdx.x & 31;
    if (warp >= BATCH + CLS) return;
    const float* row = (warp < BATCH) ? (feat + (size_t)warp * DIM)
                                      : (w + (size_t)(warp - BATCH) * DIM);
    float s = 0.0f;
    #pragma unroll
    for (int k = lane; k < DIM; k += 32) {
        float v = row[k];
        s = fmaf(v, v, s);
    }
    #pragma unroll
    for (int o = 16; o; o >>= 1) s += __shfl_xor_sync(0xffffffffu, s, o);
    if (lane == 0) {
        if (warp < BATCH) {
            g_x2[warp] = s;
        } else {
            g_w2[warp - BATCH] = s;
            atomicMax(&g_w2max_bits, __float_as_uint(s));
        }
    }
}

// ---------------------------------------------------------------- cor sum
// One warp per sample: dot(feat[b], weights[label[b]]) -> cor -> atomic sum.
__global__ void k_cor(const float* __restrict__ feat,
                      const int*   __restrict__ label,
                      const float* __restrict__ w) {
    int warp = (blockIdx.x * blockDim.x + threadIdx.x) >> 5;
    int lane = threadIdx.x & 31;
    if (warp >= BATCH) return;
    int lab = label[warp];
    const float* x  = feat + (size_t)warp * DIM;
    const float* wr = w + (size_t)lab * DIM;
    float s = 0.0f;
    #pragma unroll
    for (int k = lane; k < DIM; k += 32) s = fmaf(x[k], wr[k], s);
    #pragma unroll
    for (int o = 16; o; o >>= 1) s += __shfl_xor_sync(0xffffffffu, s, o);
    if (lane == 0) {
        float metric = g_x2[warp] + g_w2[lab] - 2.0f * s;
        float cor = expf(-metric * (1.0f / 1.2f));
        atomicAdd(&g_cor_sum, cor);
    }
}

// ---------------------------------------------------------------- scale
__global__ void k_scale() {
    float avg = fmaxf(g_cor_sum * (1.0f / (float)BATCH), 0.5f);
    g_scale3 = 3.0f * logf((float)(CLS - 1)) / avg;
}

// ---------------------------------------------------------------- fill
// One thread per float4 of output. Fast path: whole row provably underflows
// -> write zeros (store-bound). Fallback: exact fp32 dot + expf.
__global__ void k_fill(const float* __restrict__ feat,
                       const float* __restrict__ w,
                       float*       __restrict__ out) {
    long long idx = (long long)blockIdx.x * blockDim.x + threadIdx.x;
    if (idx >= (long long)BATCH * C4) return;
    int b  = (int)(idx / C4);
    int c4 = (int)(idx % C4);

    float x2   = g_x2[b];
    float wmax = __uint_as_float(g_w2max_bits);
    float xn = sqrtf(x2);
    float wn = sqrtf(wmax);
    float d  = xn - wn;

    float4 o;
    if (xn > wn && d * d > 132.0f) {      // metric/1.2 > 110 for every c -> exp == 0.0f exactly
        o = make_float4(0.0f, 0.0f, 0.0f, 0.0f);
    } else {
        // Exact fallback (not taken on this data, kept for correctness).
        float s3 = g_scale3;
        const float* x = feat + (size_t)b * DIM;
        int c = c4 * 4;
        float acc0 = 0.f, acc1 = 0.f, acc2 = 0.f, acc3 = 0.f;
        const float* w0 = w + (size_t)(c + 0) * DIM;
        const float* w1 = w + (size_t)(c + 1) * DIM;
        const float* w2 = w + (size_t)(c + 2) * DIM;
        const float* w3 = w + (size_t)(c + 3) * DIM;
        for (int k = 0; k < DIM; k++) {
            float xv = x[k];
            acc0 = fmaf(xv, w0[k], acc0);
            acc1 = fmaf(xv, w1[k], acc1);
            acc2 = fmaf(xv, w2[k], acc2);
            acc3 = fmaf(xv, w3[k], acc3);
        }
        o.x = s3 * expf(-(x2 + g_w2[c + 0] - 2.0f * acc0) * (1.0f / 1.2f));
        o.y = s3 * expf(-(x2 + g_w2[c + 1] - 2.0f * acc1) * (1.0f / 1.2f));
        o.z = s3 * expf(-(x2 + g_w2[c + 2] - 2.0f * acc2) * (1.0f / 1.2f));
        o.w = s3 * expf(-(x2 + g_w2[c + 3] - 2.0f * acc3) * (1.0f / 1.2f));
    }
    reinterpret_cast<float4*>(out)[idx] = o;
}

// ---------------------------------------------------------------- launch
extern "C" void kernel_launch(void* const* d_in, const int* in_sizes, int n_in,
                              void* d_out, int out_size) {
    const float* feat  = (const float*)d_in[0];
    const int*   label = (const int*)  d_in[1];
    const float* w     = (const float*)d_in[2];
    float*       out   = (float*)d_out;

    k_init<<<1, 1>>>();

    {   // norms: (BATCH + CLS) warps
        int warps  = BATCH + CLS;
        int blocks = (warps * 32 + 255) / 256;
        k_norms<<<blocks, 256>>>(feat, w);
    }
    {   // cor: BATCH warps
        int blocks = (BATCH * 32 + 255) / 256;
        k_cor<<<blocks, 256>>>(feat, label, w);
    }
    k_scale<<<1, 1>>>();
    {   // fill: BATCH * C4 threads (exactly 40000 blocks of 256)
        long long total = (long long)BATCH * C4;
        int blocks = (int)((total + 255) / 256);
        k_fill<<<blocks, 256>>>(feat, w, out);
    }
}

// round 2
// speedup vs baseline: 1.0526x; 1.0526x over previous
#include <cuda_runtime.h>
#include <math.h>

// PureKernalMetricLogits: out[b,c] = 3*scale*exp(-(||x_b||^2+||w_c||^2-2 x_b.w_c)/1.2)
// scale = log(C-1)/max(mean_b exp(-||x_b - w_label||^2/1.2), 0.5)
//
// Reverse triangle inequality: metric[b,c] >= (||x_b|| - ||w_c||)^2.
// If (||x_b|| - max_c||w_c||)^2 / 1.2 > 110, expf underflows to exactly 0.0f
// in BOTH the f32 reference and here -> whole row is zeros, no GEMM needed.
// Full fp32 fallback (dot + expf + scale) covers the general case.

#define BATCH 4096
#define DIM   512
#define CLS   10000
#define C4    (CLS / 4)          // 2500 float4 per output row

#define PREP_WARPS   (BATCH + CLS)          // 14096 rows, one warp each
#define PREP_WPB     8                      // warps per block
#define PREP_BLOCKS  ((PREP_WARPS + PREP_WPB - 1) / PREP_WPB)  // 1762

__device__ float g_x2[BATCH];
__device__ float g_w2[CLS];
__device__ float g_cor[BATCH];
__device__ float g_w2max;
__device__ float g_scale3;                   // 3 * log(C-1) / max(mean cor, 0.5)
__device__ unsigned int g_arrived = 0;       // self-resetting -> graph-replay safe

// ------------------------------------------------------------------ prep
// One warp per row. feat rows: x2 and cor (direct ||x-w||^2, no gather pass).
// weight rows: w2. Last block reduces w2max + mean(cor) -> scale, resets ctr.
__global__ void k_prep(const float* __restrict__ feat,
                       const int*   __restrict__ label,
                       const float* __restrict__ w) {
    int warp = blockIdx.x * PREP_WPB + (threadIdx.x >> 5);
    int lane = threadIdx.x & 31;

    if (warp < BATCH) {
        const float* x  = feat + (size_t)warp * DIM;
        const float* wr = w + (size_t)label[warp] * DIM;
        float x2 = 0.0f, d2 = 0.0f;
        #pragma unroll
        for (int k = lane; k < DIM; k += 32) {
            float xv = x[k];
            float dv = xv - wr[k];
            x2 = fmaf(xv, xv, x2);
            d2 = fmaf(dv, dv, d2);
        }
        #pragma unroll
        for (int o = 16; o; o >>= 1) {
            x2 += __shfl_xor_sync(0xffffffffu, x2, o);
            d2 += __shfl_xor_sync(0xffffffffu, d2, o);
        }
        if (lane == 0) {
            g_x2[warp]  = x2;
            g_cor[warp] = expf(-d2 * (1.0f / 1.2f));
        }
    } else if (warp < PREP_WARPS) {
        int c = warp - BATCH;
        const float* wr = w + (size_t)c * DIM;
        float s = 0.0f;
        #pragma unroll
        for (int k = lane; k < DIM; k += 32) {
            float v = wr[k];
            s = fmaf(v, v, s);
        }
        #pragma unroll
        for (int o = 16; o; o >>= 1) s += __shfl_xor_sync(0xffffffffu, s, o);
        if (lane == 0) g_w2[c] = s;
    }

    // ---- last-block reduction (deterministic tree, fixed order) ----
    __shared__ bool s_last;
    __threadfence();
    __syncthreads();
    if (threadIdx.x == 0) {
        unsigned int t = atomicAdd(&g_arrived, 1u);
        s_last = (t == (unsigned int)(gridDim.x - 1));
    }
    __syncthreads();
    if (!s_last) return;

    __shared__ float smax[256];
    __shared__ float ssum[256];
    int tid = threadIdx.x;                     // 256 threads
    float m = 0.0f;
    for (int i = tid; i < CLS; i += 256) m = fmaxf(m, g_w2[i]);
    float su = 0.0f;
    for (int i = tid; i < BATCH; i += 256) su += g_cor[i];
    smax[tid] = m;
    ssum[tid] = su;
    __syncthreads();
    #pragma unroll
    for (int o = 128; o; o >>= 1) {
        if (tid < o) {
            smax[tid] = fmaxf(smax[tid], smax[tid + o]);
            ssum[tid] += ssum[tid + o];
        }
        __syncthreads();
    }
    if (tid == 0) {
        g_w2max   = smax[0];
        float avg = fmaxf(ssum[0] * (1.0f / (float)BATCH), 0.5f);
        g_scale3  = 3.0f * logf((float)(CLS - 1)) / avg;
        g_arrived = 0;                         // reset for next graph replay
    }
}

// ------------------------------------------------------------------ fill
// grid = (5, BATCH), block = 512. One float4 store per thread, no division.
// Fast path: provable whole-row underflow -> write zeros at store BW.
__global__ void k_fill(const float* __restrict__ feat,
                       const float* __restrict__ w,
                       float*       __restrict__ out) {
    int b  = blockIdx.y;
    int c4 = blockIdx.x * blockDim.x + threadIdx.x;
    if (c4 >= C4) return;

    float x2 = g_x2[b];
    float xn = sqrtf(x2);
    float wn = sqrtf(g_w2max);
    float d  = xn - wn;

    float4 o;
    if (xn > wn && d * d > 132.0f) {   // metric/1.2 > 110 for every c -> exp == 0.0f exactly
        o = make_float4(0.0f, 0.0f, 0.0f, 0.0f);
    } else {
        // Exact fp32 fallback (never taken on this data, kept for correctness).
        float s3 = g_scale3;
        const float* x = feat + (size_t)b * DIM;
        int c = c4 * 4;
        float a0 = 0.f, a1 = 0.f, a2 = 0.f, a3 = 0.f;
        const float* w0 = w + (size_t)(c + 0) * DIM;
        const float* w1 = w + (size_t)(c + 1) * DIM;
        const float* w2 = w + (size_t)(c + 2) * DIM;
        const float* w3 = w + (size_t)(c + 3) * DIM;
        for (int k = 0; k < DIM; k++) {
            float xv = x[k];
            a0 = fmaf(xv, w0[k], a0);
            a1 = fmaf(xv, w1[k], a1);
            a2 = fmaf(xv, w2[k], a2);
            a3 = fmaf(xv, w3[k], a3);
        }
        o.x = s3 * expf(-(x2 + g_w2[c + 0] - 2.0f * a0) * (1.0f / 1.2f));
        o.y = s3 * expf(-(x2 + g_w2[c + 1] - 2.0f * a1) * (1.0f / 1.2f));
        o.z = s3 * expf(-(x2 + g_w2[c + 2] - 2.0f * a2) * (1.0f / 1.2f));
        o.w = s3 * expf(-(x2 + g_w2[c + 3] - 2.0f * a3) * (1.0f / 1.2f));
    }
    reinterpret_cast<float4*>(out)[(size_t)b * C4 + c4] = o;
}

// ------------------------------------------------------------------ launch
extern "C" void kernel_launch(void* const* d_in, const int* in_sizes, int n_in,
                              void* d_out, int out_size) {
    const float* feat  = (const float*)d_in[0];
    const int*   label = (const int*)  d_in[1];
    const float* w     = (const float*)d_in[2];
    float*       out   = (float*)d_out;

    k_prep<<<PREP_BLOCKS, PREP_WPB * 32>>>(feat, label, w);

    dim3 grid((C4 + 511) / 512, BATCH);
    k_fill<<<grid, 512>>>(feat, w, out);
}

// round 3
// speedup vs baseline: 1.3089x; 1.2435x over previous
#include <cuda_runtime.h>
#include <math.h>

// PureKernalMetricLogits: out[b,c] = 3*scale*exp(-(||x_b||^2+||w_c||^2-2 x_b.w_c)/1.2)
// scale = log(C-1)/max(mean_b exp(-||x_b - w_label_b||^2/1.2), 0.5)
//
// Reverse triangle inequality: metric[b,c] >= (||x_b|| - ||w_c||)^2.
// If (||x_b|| - max_c||w_c||)^2 / 1.2 > 110, expf underflows to exactly 0.0f
// in BOTH the f32 reference and here -> whole output row is zeros, no GEMM.
// The per-row flag is precomputed once; a full fp32 fallback path covers the
// general case (exact dot + expf + scale).

#define BATCH 4096
#define DIM   512
#define CLS   10000
#define C4    (CLS / 4)          // 2500 float4 per output row
#define D4    (DIM / 4)          // 128 float4 per input row

#define PREP_WARPS   (BATCH + CLS)                            // 14096 rows
#define PREP_WPB     8                                        // 256 thr/blk
#define PREP_BLOCKS  ((PREP_WARPS + PREP_WPB - 1) / PREP_WPB) // 1762

__device__ float g_x2[BATCH];
__device__ float g_w2[CLS];
__device__ float g_cor[BATCH];
__device__ int   g_rowzero[BATCH];           // 1 -> row provably all zeros
__device__ float g_scale3;                   // 3 * log(C-1) / max(mean cor, 0.5)
__device__ unsigned int g_arrived = 0;       // self-resetting -> graph-replay safe

// ------------------------------------------------------------------ prep
// One warp per row (float4 loads). feat rows: x2 and cor = exp(-||x-w_l||^2/1.2).
// weight rows: w2. Last arriving block reduces max(w2) + mean(cor) -> scale,
// precomputes per-row zero flags, resets the counter.
__global__ void k_prep(const float* __restrict__ feat,
                       const int*   __restrict__ label,
                       const float* __restrict__ w) {
    int warp = blockIdx.x * PREP_WPB + (threadIdx.x >> 5);
    int lane = threadIdx.x & 31;

    if (warp < BATCH) {
        const float4* x4 = reinterpret_cast<const float4*>(feat + (size_t)warp * DIM);
        const float4* w4 = reinterpret_cast<const float4*>(w + (size_t)label[warp] * DIM);
        float x2 = 0.0f, d2 = 0.0f;
        #pragma unroll
        for (int k = lane; k < D4; k += 32) {
            float4 xv = x4[k];
            float4 wv = w4[k];
            x2 = fmaf(xv.x, xv.x, x2); x2 = fmaf(xv.y, xv.y, x2);
            x2 = fmaf(xv.z, xv.z, x2); x2 = fmaf(xv.w, xv.w, x2);
            float dx = xv.x - wv.x, dy = xv.y - wv.y;
            float dz = xv.z - wv.z, dw = xv.w - wv.w;
            d2 = fmaf(dx, dx, d2); d2 = fmaf(dy, dy, d2);
            d2 = fmaf(dz, dz, d2); d2 = fmaf(dw, dw, d2);
        }
        #pragma unroll
        for (int o = 16; o; o >>= 1) {
            x2 += __shfl_xor_sync(0xffffffffu, x2, o);
            d2 += __shfl_xor_sync(0xffffffffu, d2, o);
        }
        if (lane == 0) {
            g_x2[warp]  = x2;
            g_cor[warp] = expf(-d2 * (1.0f / 1.2f));
        }
    } else if (warp < PREP_WARPS) {
        int c = warp - BATCH;
        const float4* w4 = reinterpret_cast<const float4*>(w + (size_t)c * DIM);
        float s = 0.0f;
        #pragma unroll
        for (int k = lane; k < D4; k += 32) {
            float4 v = w4[k];
            s = fmaf(v.x, v.x, s); s = fmaf(v.y, v.y, s);
            s = fmaf(v.z, v.z, s); s = fmaf(v.w, v.w, s);
        }
        #pragma unroll
        for (int o = 16; o; o >>= 1) s += __shfl_xor_sync(0xffffffffu, s, o);
        if (lane == 0) g_w2[c] = s;
    }

    // ---- last-block reduction (deterministic, fixed order) ----
    __shared__ bool s_last;
    __threadfence();
    __syncthreads();
    if (threadIdx.x == 0) {
        unsigned int t = atomicAdd(&g_arrived, 1u);
        s_last = (t == (unsigned int)(gridDim.x - 1));
    }
    __syncthreads();
    if (!s_last) return;

    __shared__ float smax[256];
    __shared__ float ssum[256];
    int tid = threadIdx.x;                     // 256 threads
    float m = 0.0f;
    for (int i = tid; i < CLS; i += 256) m = fmaxf(m, g_w2[i]);
    float su = 0.0f;
    for (int i = tid; i < BATCH; i += 256) su += g_cor[i];
    smax[tid] = m;
    ssum[tid] = su;
    __syncthreads();
    #pragma unroll
    for (int o = 128; o; o >>= 1) {
        if (tid < o) {
            smax[tid] = fmaxf(smax[tid], smax[tid + o]);
            ssum[tid] += ssum[tid + o];
        }
        __syncthreads();
    }
    if (tid == 0) {
        float avg = fmaxf(ssum[0] * (1.0f / (float)BATCH), 0.5f);
        g_scale3  = 3.0f * logf((float)(CLS - 1)) / avg;
        g_arrived = 0;                         // reset for next graph replay
    }
    __syncthreads();
    float wn = sqrtf(smax[0]);
    for (int b = tid; b < BATCH; b += 256) {
        float xn = sqrtf(g_x2[b]);
        float d  = xn - wn;
        // metric/1.2 > 110 for every class c  ->  exp underflows to exactly 0.0f
        g_rowzero[b] = (xn > wn && d * d > 132.0f) ? 1 : 0;
    }
}

// ------------------------------------------------------------------ fill
// One block per output row (grid=4096, block=512). Uniform per-row flag,
// 5 strided float4 streaming stores per thread. Zero per-thread math on the
// fast path. Fallback: exact fp32 dot + expf (never taken on this data).
__global__ void __launch_bounds__(512) k_fill(const float* __restrict__ feat,
                                              const float* __restrict__ w,
                                              float*       __restrict__ out) {
    int b   = blockIdx.x;
    int tid = threadIdx.x;
    float4* orow = reinterpret_cast<float4*>(out) + (size_t)b * C4;

    if (g_rowzero[b]) {
        const float4 z = make_float4(0.0f, 0.0f, 0.0f, 0.0f);
        #pragma unroll
        for (int j = 0; j < 5; j++) {
            int idx = j * 512 + tid;
            if (idx < C4) __stcs(orow + idx, z);
        }
        return;
    }

    // ---- exact fp32 fallback ----
    float x2 = g_x2[b];
    float s3 = g_scale3;
    const float4* x4 = reinterpret_cast<const float4*>(feat + (size_t)b * DIM);
    for (int j = 0; j < 5; j++) {
        int c4 = j * 512 + tid;
        if (c4 >= C4) break;
        int c = c4 * 4;
        float a0 = 0.f, a1 = 0.f, a2 = 0.f, a3 = 0.f;
        const float4* w0 = reinterpret_cast<const float4*>(w + (size_t)(c + 0) * DIM);
        const float4* w1 = reinterpret_cast<const float4*>(w + (size_t)(c + 1) * DIM);
        const float4* w2 = reinterpret_cast<const float4*>(w + (size_t)(c + 2) * DIM);
        const float4* w3 = reinterpret_cast<const float4*>(w + (size_t)(c + 3) * DIM);
        for (int k = 0; k < D4; k++) {
            float4 xv = x4[k];
            float4 v0 = w0[k], v1 = w1[k], v2 = w2[k], v3 = w3[k];
            a0 = fmaf(xv.x, v0.x, a0); a0 = fmaf(xv.y, v0.y, a0);
            a0 = fmaf(xv.z, v0.z, a0); a0 = fmaf(xv.w, v0.w, a0);
            a1 = fmaf(xv.x, v1.x, a1); a1 = fmaf(xv.y, v1.y, a1);
            a1 = fmaf(xv.z, v1.z, a1); a1 = fmaf(xv.w, v1.w, a1);
            a2 = fmaf(xv.x, v2.x, a2); a2 = fmaf(xv.y, v2.y, a2);
            a2 = fmaf(xv.z, v2.z, a2); a2 = fmaf(xv.w, v2.w, a2);
            a3 = fmaf(xv.x, v3.x, a3); a3 = fmaf(xv.y, v3.y, a3);
            a3 = fmaf(xv.z, v3.z, a3); a3 = fmaf(xv.w, v3.w, a3);
        }
        float4 o;
        o.x = s3 * expf(-(x2 + g_w2[c + 0] - 2.0f * a0) * (1.0f / 1.2f));
        o.y = s3 * expf(-(x2 + g_w2[c + 1] - 2.0f * a1) * (1.0f / 1.2f));
        o.z = s3 * expf(-(x2 + g_w2[c + 2] - 2.0f * a2) * (1.0f / 1.2f));
        o.w = s3 * expf(-(x2 + g_w2[c + 3] - 2.0f * a3) * (1.0f / 1.2f));
        orow[c4] = o;
    }
}

// ------------------------------------------------------------------ launch
extern "C" void kernel_launch(void* const* d_in, const int* in_sizes, int n_in,
                              void* d_out, int out_size) {
    const float* feat  = (const float*)d_in[0];
    const int*   label = (const int*)  d_in[1];
    const float* w     = (const float*)d_in[2];
    float*       out   = (float*)d_out;

    k_prep<<<PREP_BLOCKS, PREP_WPB * 32>>>(feat, label, w);
    k_fill<<<BATCH, 512>>>(feat, w, out);
}

// round 4
// speedup vs baseline: 1.3182x; 1.0071x over previous
#include <cuda_runtime.h>
#include <math.h>

// PureKernalMetricLogits: out[b,c] = 3*scale*exp(-(||x_b||^2+||w_c||^2-2 x_b.w_c)/1.2)
// scale = log(C-1)/max(mean_b exp(-||x_b - w_label_b||^2/1.2), 0.5)
//
// Reverse triangle inequality: metric[b,c] >= (||x_b|| - ||w_c||)^2.
// If (||x_b|| - max_c||w_c||)^2 / 1.2 > 110, expf underflows to exactly 0.0f
// in BOTH the f32 reference and here -> whole output row is zeros, no GEMM.
// Per-row flags are precomputed; full fp32 fallback covers the general case.

#define BATCH 4096
#define DIM   512
#define CLS   10000
#define C4    (CLS / 4)          // 2500 float4 per output row
#define D4    (DIM / 4)          // 128 float4 per input row

#define NROWS        (BATCH + CLS)       // 14096 rows total
#define PREP_WPB     8                   // 256 threads per block
#define PREP_BLOCKS  881                 // 7048 warps, exactly 2 rows each (one wave)

__device__ float g_x2[BATCH];
__device__ float g_w2[CLS];
__device__ float g_cor[BATCH];
__device__ int   g_rowzero[BATCH];           // 1 -> row provably all zeros
__device__ float g_scale3;                   // 3 * log(C-1) / max(mean cor, 0.5)
__device__ unsigned int g_arrived = 0;       // self-resetting -> graph-replay safe

// ---- per-warp row processor -------------------------------------------
__device__ __forceinline__ void do_row(int row, int lane,
                                       const float* __restrict__ feat,
                                       const int*   __restrict__ label,
                                       const float* __restrict__ w) {
    if (row < BATCH) {
        const float4* x4 = reinterpret_cast<const float4*>(feat + (size_t)row * DIM);
        const float4* w4 = reinterpret_cast<const float4*>(w + (size_t)label[row] * DIM);
        float x2 = 0.0f, d2 = 0.0f;
        #pragma unroll
        for (int k = lane; k < D4; k += 32) {
            float4 xv = x4[k];
            float4 wv = w4[k];
            x2 = fmaf(xv.x, xv.x, x2); x2 = fmaf(xv.y, xv.y, x2);
            x2 = fmaf(xv.z, xv.z, x2); x2 = fmaf(xv.w, xv.w, x2);
            float dx = xv.x - wv.x, dy = xv.y - wv.y;
            float dz = xv.z - wv.z, dw = xv.w - wv.w;
            d2 = fmaf(dx, dx, d2); d2 = fmaf(dy, dy, d2);
            d2 = fmaf(dz, dz, d2); d2 = fmaf(dw, dw, d2);
        }
        #pragma unroll
        for (int o = 16; o; o >>= 1) {
            x2 += __shfl_xor_sync(0xffffffffu, x2, o);
            d2 += __shfl_xor_sync(0xffffffffu, d2, o);
        }
        if (lane == 0) {
            g_x2[row]  = x2;
            g_cor[row] = expf(-d2 * (1.0f / 1.2f));
        }
    } else {
        int c = row - BATCH;
        const float4* w4 = reinterpret_cast<const float4*>(w + (size_t)c * DIM);
        float s = 0.0f;
        #pragma unroll
        for (int k = lane; k < D4; k += 32) {
            float4 v = w4[k];
            s = fmaf(v.x, v.x, s); s = fmaf(v.y, v.y, s);
            s = fmaf(v.z, v.z, s); s = fmaf(v.w, v.w, s);
        }
        #pragma unroll
        for (int o = 16; o; o >>= 1) s += __shfl_xor_sync(0xffffffffu, s, o);
        if (lane == 0) g_w2[c] = s;
    }
}

// ------------------------------------------------------------------ prep
// 7048 warps, 2 consecutive rows each (balanced single wave). Last arriving
// block reduces max(w2) + mean(cor) -> scale + per-row zero flags.
__global__ void __launch_bounds__(256) k_prep(const float* __restrict__ feat,
                                              const int*   __restrict__ label,
                                              const float* __restrict__ w) {
    int warp = blockIdx.x * PREP_WPB + (threadIdx.x >> 5);
    int lane = threadIdx.x & 31;
    int r0   = warp * 2;

    do_row(r0,     lane, feat, label, w);
    do_row(r0 + 1, lane, feat, label, w);

    // ---- last-block reduction (deterministic, fixed order) ----
    __shared__ bool s_last;
    __threadfence();
    __syncthreads();
    if (threadIdx.x == 0) {
        unsigned int t = atomicAdd(&g_arrived, 1u);
        s_last = (t == (unsigned int)(gridDim.x - 1));
    }
    __syncthreads();
    if (!s_last) return;

    __shared__ float smax[256];
    __shared__ float ssum[256];
    int tid = threadIdx.x;                     // 256 threads
    float m = 0.0f;
    for (int i = tid; i < CLS; i += 256) m = fmaxf(m, g_w2[i]);
    float su = 0.0f;
    for (int i = tid; i < BATCH; i += 256) su += g_cor[i];
    smax[tid] = m;
    ssum[tid] = su;
    __syncthreads();
    #pragma unroll
    for (int o = 128; o; o >>= 1) {
        if (tid < o) {
            smax[tid] = fmaxf(smax[tid], smax[tid + o]);
            ssum[tid] += ssum[tid + o];
        }
        __syncthreads();
    }
    if (tid == 0) {
        float avg = fmaxf(ssum[0] * (1.0f / (float)BATCH), 0.5f);
        g_scale3  = 3.0f * logf((float)(CLS - 1)) / avg;
        g_arrived = 0;                         // reset for next graph replay
    }
    __syncthreads();
    float wn = sqrtf(smax[0]);
    for (int b = tid; b < BATCH; b += 256) {
        float xn = sqrtf(g_x2[b]);
        float d  = xn - wn;
        // metric/1.2 > 110 for every class c  ->  exp underflows to exactly 0.0f
        g_rowzero[b] = (xn > wn && d * d > 132.0f) ? 1 : 0;
    }
}

// ------------------------------------------------------------------ fill
// One block per output row (grid=4096, block=512). Uniform per-row flag,
// 5 strided float4 streaming stores per thread, zero math on the fast path.
// Fallback: exact fp32 dot + expf (never taken on this data).
__global__ void __launch_bounds__(512) k_fill(const float* __restrict__ feat,
                                              const float* __restrict__ w,
                                              float*       __restrict__ out) {
    int b   = blockIdx.x;
    int tid = threadIdx.x;
    float4* orow = reinterpret_cast<float4*>(out) + (size_t)b * C4;

    if (g_rowzero[b]) {
        const float4 z = make_float4(0.0f, 0.0f, 0.0f, 0.0f);
        #pragma unroll
        for (int j = 0; j < 5; j++) {
            int idx = j * 512 + tid;
            if (idx < C4) __stcs(orow + idx, z);
        }
        return;
    }

    // ---- exact fp32 fallback ----
    float x2 = g_x2[b];
    float s3 = g_scale3;
    const float4* x4 = reinterpret_cast<const float4*>(feat + (size_t)b * DIM);
    for (int j = 0; j < 5; j++) {
        int c4 = j * 512 + tid;
        if (c4 >= C4) break;
        int c = c4 * 4;
        float a0 = 0.f, a1 = 0.f, a2 = 0.f, a3 = 0.f;
        const float4* w0 = reinterpret_cast<const float4*>(w + (size_t)(c + 0) * DIM);
        const float4* w1 = reinterpret_cast<const float4*>(w + (size_t)(c + 1) * DIM);
        const float4* w2 = reinterpret_cast<const float4*>(w + (size_t)(c + 2) * DIM);
        const float4* w3 = reinterpret_cast<const float4*>(w + (size_t)(c + 3) * DIM);
        for (int k = 0; k < D4; k++) {
            float4 xv = x4[k];
            float4 v0 = w0[k], v1 = w1[k], v2 = w2[k], v3 = w3[k];
            a0 = fmaf(xv.x, v0.x, a0); a0 = fmaf(xv.y, v0.y, a0);
            a0 = fmaf(xv.z, v0.z, a0); a0 = fmaf(xv.w, v0.w, a0);
            a1 = fmaf(xv.x, v1.x, a1); a1 = fmaf(xv.y, v1.y, a1);
            a1 = fmaf(xv.z, v1.z, a1); a1 = fmaf(xv.w, v1.w, a1);
            a2 = fmaf(xv.x, v2.x, a2); a2 = fmaf(xv.y, v2.y, a2);
            a2 = fmaf(xv.z, v2.z, a2); a2 = fmaf(xv.w, v2.w, a2);
            a3 = fmaf(xv.x, v3.x, a3); a3 = fmaf(xv.y, v3.y, a3);
            a3 = fmaf(xv.z, v3.z, a3); a3 = fmaf(xv.w, v3.w, a3);
        }
        float4 o;
        o.x = s3 * expf(-(x2 + g_w2[c + 0] - 2.0f * a0) * (1.0f / 1.2f));
        o.y = s3 * expf(-(x2 + g_w2[c + 1] - 2.0f * a1) * (1.0f / 1.2f));
        o.z = s3 * expf(-(x2 + g_w2[c + 2] - 2.0f * a2) * (1.0f / 1.2f));
        o.w = s3 * expf(-(x2 + g_w2[c + 3] - 2.0f * a3) * (1.0f / 1.2f));
        orow[c4] = o;
    }
}

// ------------------------------------------------------------------ launch
extern "C" void kernel_launch(void* const* d_in, const int* in_sizes, int n_in,
                              void* d_out, int out_size) {
    const float* feat  = (const float*)d_in[0];
    const int*   label = (const int*)  d_in[1];
    const float* w     = (const float*)d_in[2];
    float*       out   = (float*)d_out;

    k_prep<<<PREP_BLOCKS, PREP_WPB * 32>>>(feat, label, w);
    k_fill<<<BATCH, 512>>>(feat, w, out);
}